// round 4
// baseline (speedup 1.0000x reference)
#include <cuda_runtime.h>
#include <math.h>
#include <stdint.h>

#define BB   512
#define TT   256
#define PP   61
#define HE   256
#define LATD 512
#define DECD 32
#define TBAR 16
#define NROWS (BB*TT)   // 131072
#define NBLK 128

// ---------------- scratch ----------------
__device__ float g_enc[(size_t)NROWS*512];     // (B*T, 2H)
__device__ float g_h[2][2][BB*HE];
__device__ float g_emb[(size_t)BB*TBAR*DECD];

// per-group barriers: group = (dir,bt), 16 groups of 8 blocks
__device__ unsigned g_cnt[16];
__device__ volatile unsigned g_sns[16];

typedef unsigned long long u64;

__device__ __forceinline__ float sigmoidf_(float v){ return 1.f/(1.f+__expf(-v)); }
__device__ __forceinline__ void upk2(u64 v, float &lo, float &hi){
    asm("mov.b64 {%0,%1}, %2;" : "=f"(lo), "=f"(hi) : "l"(v));
}
__device__ __forceinline__ void ffma2(u64 &d, u64 a, u64 b){
    asm("fma.rn.f32x2 %0, %1, %2, %0;" : "+l"(d) : "l"(a), "l"(b));
}

// ---------------- mma.sync tf32 helpers (baseline PTX, sm_80+) ----------------
__device__ __forceinline__ void mma8(float &d0, float &d1, float &d2, float &d3,
    uint32_t a0, uint32_t a1, uint32_t a2, uint32_t a3, uint32_t b0, uint32_t b1){
    asm volatile("mma.sync.aligned.m16n8k8.row.col.f32.tf32.tf32.f32 "
        "{%0,%1,%2,%3},{%4,%5,%6,%7},{%8,%9},{%0,%1,%2,%3};"
        : "+f"(d0),"+f"(d1),"+f"(d2),"+f"(d3)
        : "r"(a0),"r"(a1),"r"(a2),"r"(a3),"r"(b0),"r"(b1));
}
__device__ __forceinline__ void tfsplit(float v, uint32_t &h, uint32_t &l){
    uint32_t hb = __float_as_uint(v) & 0xFFFFE000u;
    h = hb;
    l = __float_as_uint(v - __uint_as_float(hb));
}

// ---------------- persistent bidirectional encoder ----------------
// 128 blocks x 256 threads; block: dir|bt|nt; tile 64 rows x 128 gate-cols
// col n of tile -> gate g = n>>5, hidden j = j0 + (n&31)  (gate-strided: conflict-free dup-B)
__global__ void __launch_bounds__(256, 1) enc_persist_kernel(
    const float* __restrict__ x,
    const float* __restrict__ Wih_f, const float* __restrict__ Whh_f, const float* __restrict__ b_f,
    const float* __restrict__ Wih_b, const float* __restrict__ Whh_b, const float* __restrict__ b_b)
{
    const int bid = blockIdx.x;
    const int dir = bid >> 6;
    const int bt  = (bid >> 3) & 7;
    const int nt  = bid & 7;
    const int b0 = bt*64, j0 = nt*32;
    const int grp = bid >> 3;             // dir*8 + bt
    const float* Wih  = dir ? Wih_b : Wih_f;
    const float* Whh  = dir ? Whh_b : Whh_f;
    const float* bias = dir ? b_b   : b_f;

    __shared__ float sA[8][68];
    __shared__ float sBd[8][264];         // duplicated B: col n at [2n],[2n+1]
    __shared__ unsigned s_sense;

    const int tid = threadIdx.x;
    if (tid == 0) s_sense = g_sns[grp];

    for (int i = tid; i < 64*32; i += 256){
        int r = i >> 5, j = j0 + (i & 31);
        g_h[dir][0][(size_t)(b0+r)*HE + j] = 0.f;
    }

#define GRID_BAR() do {                                            \
        __threadfence();                                           \
        __syncthreads();                                           \
        if (tid == 0){                                             \
            unsigned my = s_sense;                                 \
            unsigned old = atomicAdd(&g_cnt[grp], 1u);             \
            if (old == 7u){                                        \
                g_cnt[grp] = 0;                                    \
                __threadfence();                                   \
                g_sns[grp] = my ^ 1u;                              \
            } else {                                               \
                while (g_sns[grp] == my) __nanosleep(32);          \
            }                                                      \
            s_sense = my ^ 1u;                                     \
        }                                                          \
        __syncthreads();                                           \
    } while(0)

    GRID_BAR();

    const int tx = tid & 31;
    const int ty = tid >> 5;
    const int jj = j0 + tx;

    const int am  = tid >> 2;            // A row 0..63
    const int akb = (tid & 3) * 2;
    const int bn  = tid >> 1;            // B col 0..127
    const int bkb = (tid & 1) * 4;
    const int wg  = bn >> 5, wj = j0 + (bn & 31);   // gate-strided mapping
    const float* whhrow = Whh + (size_t)(wg*HE + wj)*HE;
    const float* wihrow = Wih + (size_t)(wg*HE + wj)*PP;

    float creg[8];
    #pragma unroll
    for (int r=0;r<8;r++) creg[r] = 0.f;
    float biasv[4];
    #pragma unroll
    for (int g=0; g<4; g++) biasv[g] = bias[g*HE + jj];

    float ra[2], rb[4];

    for (int t=0; t<TT; t++){
        const int tpos = dir ? (TT-1-t) : t;
        const float* hprev = g_h[dir][t&1];
        float* hnext = g_h[dir][(t+1)&1];
        const float* hrow = hprev + (size_t)(b0+am)*HE;
        const float* xrow = x + ((size_t)(b0+am)*TT + tpos)*PP;

        u64 acc[4][4];
        #pragma unroll
        for (int p=0;p<4;p++)
            #pragma unroll
            for (int c=0;c<4;c++) acc[p][c] = 0ull;

        auto fetch = [&](int k0){
            if (k0 < HE){
                float2 v = __ldcg((const float2*)(hrow + k0 + akb));
                ra[0]=v.x; ra[1]=v.y;
                float4 w = __ldg((const float4*)(whhrow + k0 + bkb));
                rb[0]=w.x; rb[1]=w.y; rb[2]=w.z; rb[3]=w.w;
            } else {
                #pragma unroll
                for (int i=0;i<2;i++){ int ko = k0 + akb + i - HE;
                    ra[i] = (ko < PP) ? __ldg(xrow + ko) : 0.f; }
                #pragma unroll
                for (int i=0;i<4;i++){ int ko = k0 + bkb + i - HE;
                    rb[i] = (ko < PP) ? __ldg(wihrow + ko) : 0.f; }
            }
        };

        fetch(0);
        for (int ch=0; ch<40; ch++){
            __syncthreads();
            #pragma unroll
            for (int i=0;i<2;i++) sA[akb+i][am] = ra[i];
            #pragma unroll
            for (int i=0;i<4;i++){ sBd[bkb+i][2*bn] = rb[i]; sBd[bkb+i][2*bn+1] = rb[i]; }
            __syncthreads();
            if (ch+1 < 40) fetch((ch+1)*8);
            #pragma unroll
            for (int kk=0;kk<8;kk++){
                const ulonglong2 av0 = *(const ulonglong2*)&sA[kk][ty*8];
                const ulonglong2 av1 = *(const ulonglong2*)&sA[kk][ty*8+4];
                u64 ap[4] = { av0.x, av0.y, av1.x, av1.y };
                u64 bg[4];
                #pragma unroll
                for (int gI=0;gI<4;gI++) bg[gI] = *(const u64*)&sBd[kk][(gI*32+tx)*2];
                #pragma unroll
                for (int p=0;p<4;p++)
                    #pragma unroll
                    for (int c=0;c<4;c++) ffma2(acc[p][c], ap[p], bg[c]);
            }
        }

        #pragma unroll
        for (int p=0;p<4;p++){
            float gi[2], gf[2], gg[2], go[2];
            upk2(acc[p][0], gi[0], gi[1]);
            upk2(acc[p][1], gf[0], gf[1]);
            upk2(acc[p][2], gg[0], gg[1]);
            upk2(acc[p][3], go[0], go[1]);
            #pragma unroll
            for (int hh=0; hh<2; hh++){
                const int rloc = 2*p + hh;
                const int gb = b0 + ty*8 + rloc;
                float iv = sigmoidf_(gi[hh] + biasv[0]);
                float fv = sigmoidf_(gf[hh] + biasv[1]);
                float gv = tanhf    (gg[hh] + biasv[2]);
                float ov = sigmoidf_(go[hh] + biasv[3]);
                float cn = fv*creg[rloc] + iv*gv;
                float hn = ov*tanhf(cn);
                creg[rloc] = cn;
                hnext[(size_t)gb*HE + jj] = hn;
                g_enc[((size_t)gb*TT + tpos)*512 + dir*HE + jj] = hn;
            }
        }
        GRID_BAR();
    }
#undef GRID_BAR
}

// ---------------- encoderOut: mma.sync tf32 3-term GEMM + split/softplus ----------------
// 512 thr / 16 warps; tile M=128 x N=256; K=512 in 16 chunks of 32, double-buffered raw smem
#define EO_ASZ 4096                 // A chunk floats (128x32)
#define EO_BSZ 8192                 // B chunk floats (256x32)
#define EO_STG (EO_ASZ+EO_BSZ)      // 12288 floats / stage
#define EO_SMEM (2*EO_STG*4)        // 98304 bytes

__global__ void __launch_bounds__(512,1) encout_mma_kernel(
    const float* __restrict__ Wout, const float* __restrict__ bout,
    float* __restrict__ mu_out, float* __restrict__ lv_out)
{
    extern __shared__ float sm[];
    const int tid = threadIdx.x, lane = tid & 31, wid = tid >> 5;
    const int wm = wid & 3, wn = wid >> 2;       // m-quarter(32 rows), n-slice(64 cols)
    const int n0 = blockIdx.x*256, r0 = blockIdx.y*128;
    const int g = lane >> 2, t4 = lane & 3;

    float acc[2][8][4];
    #pragma unroll
    for (int a=0;a<2;a++)
        #pragma unroll
        for (int b=0;b<8;b++)
            #pragma unroll
            for (int c=0;c<4;c++) acc[a][b][c] = 0.f;

    // staging assignments (fragment-permuted layout)
    const float* a_src[2]; int a_dst[2];
    #pragma unroll
    for (int j=0;j<2;j++){
        int idx = j*512 + tid;
        int m = idx>>3, f4 = idx&7, kt = f4>>1, q = f4&1;
        a_src[j] = g_enc + (size_t)(r0+m)*512 + f4*4;
        a_dst[j] = (kt*8 + (m>>4))*128 + ((m>>3)&1) + 2*q + (m&7)*16;
    }
    const float* b_src[4]; int b_dst[4];
    #pragma unroll
    for (int j=0;j<4;j++){
        int idx = j*512 + tid;
        int n = idx>>3, f4 = idx&7, kt = f4>>1, q = f4&1;
        b_src[j] = Wout + (size_t)(n0+n)*512 + f4*4;
        b_dst[j] = (kt*32 + (n>>3))*64 + q + (n&7)*8;
    }

    auto stage_st = [&](int s, const float4* av, const float4* bv){
        float* base = sm + s*EO_STG;
        #pragma unroll
        for (int j=0;j<2;j++){
            float* d = base + a_dst[j];
            d[0]=av[j].x; d[4]=av[j].y; d[8]=av[j].z; d[12]=av[j].w;
        }
        float* bb = base + EO_ASZ;
        #pragma unroll
        for (int j=0;j<4;j++){
            float* d = bb + b_dst[j];
            d[0]=bv[j].x; d[2]=bv[j].y; d[4]=bv[j].z; d[6]=bv[j].w;
        }
    };

    {   // prologue: stage chunk 0
        float4 av[2], bv[4];
        #pragma unroll
        for (int j=0;j<2;j++) av[j] = __ldg((const float4*)(a_src[j]));
        #pragma unroll
        for (int j=0;j<4;j++) bv[j] = __ldg((const float4*)(b_src[j]));
        stage_st(0, av, bv);
    }
    __syncthreads();

    for (int c=0;c<16;c++){
        float4 av[2], bv[4];
        if (c+1 < 16){
            #pragma unroll
            for (int j=0;j<2;j++) av[j] = __ldg((const float4*)(a_src[j] + (c+1)*32));
            #pragma unroll
            for (int j=0;j<4;j++) bv[j] = __ldg((const float4*)(b_src[j] + (c+1)*32));
        }
        const float* SA = sm + (c&1)*EO_STG;
        const float* SB = SA + EO_ASZ;
        #pragma unroll
        for (int kt=0;kt<4;kt++){
            uint32_t ah[2][4], al[2][4];
            #pragma unroll
            for (int mt=0;mt<2;mt++){
                float4 ar = *(const float4*)&SA[(kt*8 + wm*2 + mt)*128 + lane*4];
                tfsplit(ar.x, ah[mt][0], al[mt][0]);
                tfsplit(ar.y, ah[mt][1], al[mt][1]);
                tfsplit(ar.z, ah[mt][2], al[mt][2]);
                tfsplit(ar.w, ah[mt][3], al[mt][3]);
            }
            #pragma unroll
            for (int ntI=0;ntI<8;ntI++){
                float2 br = *(const float2*)&SB[(kt*32 + wn*8 + ntI)*64 + lane*2];
                uint32_t bh0,bl0,bh1,bl1;
                tfsplit(br.x, bh0, bl0);
                tfsplit(br.y, bh1, bl1);
                #pragma unroll
                for (int mt=0;mt<2;mt++){
                    mma8(acc[mt][ntI][0],acc[mt][ntI][1],acc[mt][ntI][2],acc[mt][ntI][3],
                         ah[mt][0],ah[mt][1],ah[mt][2],ah[mt][3], bh0,bh1);
                    mma8(acc[mt][ntI][0],acc[mt][ntI][1],acc[mt][ntI][2],acc[mt][ntI][3],
                         ah[mt][0],ah[mt][1],ah[mt][2],ah[mt][3], bl0,bl1);
                    mma8(acc[mt][ntI][0],acc[mt][ntI][1],acc[mt][ntI][2],acc[mt][ntI][3],
                         al[mt][0],al[mt][1],al[mt][2],al[mt][3], bh0,bh1);
                }
            }
        }
        if (c+1 < 16) stage_st((c+1)&1, av, bv);
        __syncthreads();
    }

    // epilogue
    const int colbase = n0 + wn*64;
    #pragma unroll
    for (int mt=0;mt<2;mt++){
        const size_t raRow = (size_t)r0 + wm*32 + mt*16 + g;
        #pragma unroll
        for (int ntI=0;ntI<8;ntI++){
            const int col = colbase + ntI*8 + t4*2;
            const float bb0 = __ldg(bout + col), bb1 = __ldg(bout + col + 1);
            float v0 = acc[mt][ntI][0] + bb0, v1 = acc[mt][ntI][1] + bb1;
            float v2 = acc[mt][ntI][2] + bb0, v3 = acc[mt][ntI][3] + bb1;
            if (n0 < LATD){
                *(float2*)(mu_out + raRow*LATD + col)     = make_float2(v0, v1);
                *(float2*)(mu_out + (raRow+8)*LATD + col) = make_float2(v2, v3);
            } else {
                v0 = (v0>20.f)?v0:log1pf(__expf(v0));
                v1 = (v1>20.f)?v1:log1pf(__expf(v1));
                v2 = (v2>20.f)?v2:log1pf(__expf(v2));
                v3 = (v3>20.f)?v3:log1pf(__expf(v3));
                *(float2*)(lv_out + raRow*LATD + (col-LATD))     = make_float2(v0, v1);
                *(float2*)(lv_out + (raRow+8)*LATD + (col-LATD)) = make_float2(v2, v3);
            }
        }
    }
}

// ---------------- z projection ----------------
__global__ void __launch_bounds__(256) zproj_kernel(
    const float* __restrict__ mu, const float* __restrict__ lv, const float* __restrict__ eps,
    const float* __restrict__ Wz, const float* __restrict__ bz, float* __restrict__ zout)
{
    const int r0 = blockIdx.x*128;
    __shared__ float sA[8*132], sB[8*33];
    const int tid = threadIdx.x, tx = tid&15, ty = tid>>4;
    const int m = tid>>1, kb = (tid&1)*4;
    const size_t rr = (size_t)r0 + m;
    const int bidx = (int)(rr >> 8);
    const float* murow  = mu  + rr*LATD;
    const float* lvrow  = lv  + rr*LATD;
    const float* epsrow = eps + (size_t)bidx*LATD;
    const int bnn = tid>>3, bkk = tid&7;

    float acc[8][2] = {};
    float ra[4], rb;
    auto fetch = [&](int k0){
        float4 m4 = *(const float4*)&murow[k0+kb];
        float4 l4 = *(const float4*)&lvrow[k0+kb];
        float4 e4 = *(const float4*)&epsrow[k0+kb];
        ra[0] = m4.x + e4.x*__expf(2.f*l4.x);
        ra[1] = m4.y + e4.y*__expf(2.f*l4.y);
        ra[2] = m4.z + e4.z*__expf(2.f*l4.z);
        ra[3] = m4.w + e4.w*__expf(2.f*l4.w);
        rb = Wz[(size_t)bnn*LATD + k0 + bkk];
    };
    fetch(0);
    for (int ch=0; ch<64; ch++){
        __syncthreads();
        #pragma unroll
        for (int i=0;i<4;i++) sA[(kb+i)*132+m] = ra[i];
        sB[bkk*33 + bnn] = rb;
        __syncthreads();
        if (ch<63) fetch((ch+1)*8);
        #pragma unroll
        for (int kk=0;kk<8;kk++){
            float4 a0 = *(const float4*)&sA[kk*132 + ty*8];
            float4 a1 = *(const float4*)&sA[kk*132 + ty*8 + 4];
            float a[8] = {a0.x,a0.y,a0.z,a0.w,a1.x,a1.y,a1.z,a1.w};
            float bv0 = sB[kk*33 + tx*2 + 0];
            float bv1 = sB[kk*33 + tx*2 + 1];
            #pragma unroll
            for (int r=0;r<8;r++){
                acc[r][0] = fmaf(a[r], bv0, acc[r][0]);
                acc[r][1] = fmaf(a[r], bv1, acc[r][1]);
            }
        }
    }
    #pragma unroll
    for (int ri=0;ri<8;ri++){
        const size_t r = r0 + ty*8 + ri;
        #pragma unroll
        for (int ci=0;ci<2;ci++){
            const int col = tx*2 + ci;
            zout[r*DECD + col] = acc[ri][ci] + bz[col];
        }
    }
}

// ---------------- conductor LSTM ----------------
__global__ void __launch_bounds__(256) conductor_kernel(
    const float* __restrict__ zout, const float* __restrict__ Wih,
    const float* __restrict__ Whh, const float* __restrict__ bias)
{
    __shared__ float sWi[128*33], sWh[128*33], sb[128];
    __shared__ float sh[8*33], sc[8*33], sz[8*33];
    const int tid = threadIdx.x;
    const int b0 = blockIdx.x*8;
    for (int i=tid; i<128*32; i+=256){ int cc=i>>5, k=i&31; sWi[cc*33+k]=Wih[i]; sWh[cc*33+k]=Whh[i]; }
    if (tid < 128) sb[tid] = bias[tid];
    { int mm=tid>>5, k=tid&31; sh[mm*33+k]=0.f; sc[mm*33+k]=0.f; }
    __syncthreads();

    const int j  = tid & 31;
    const int m  = tid >> 5;
    for (int t=0; t<TBAR; t++){
        { int mm=tid>>5, k=tid&31;
          sz[mm*33+k] = zout[((size_t)(b0+mm)*TT + t)*DECD + k]; }
        __syncthreads();
        float a0=sb[j], a1=sb[32+j], a2=sb[64+j], a3=sb[96+j];
        #pragma unroll
        for (int k=0;k<32;k++){
            float zv = sz[m*33+k], hv = sh[m*33+k];
            a0 += zv*sWi[( j   )*33+k] + hv*sWh[( j   )*33+k];
            a1 += zv*sWi[(32+j)*33+k]  + hv*sWh[(32+j)*33+k];
            a2 += zv*sWi[(64+j)*33+k]  + hv*sWh[(64+j)*33+k];
            a3 += zv*sWi[(96+j)*33+k]  + hv*sWh[(96+j)*33+k];
        }
        float iv=sigmoidf_(a0), fv=sigmoidf_(a1), gv=tanhf(a2), ov=sigmoidf_(a3);
        float cn = fv*sc[m*33+j] + iv*gv;
        float hn = ov*tanhf(cn);
        __syncthreads();
        sh[m*33+j]=hn; sc[m*33+j]=cn;
        g_emb[((size_t)(b0+m)*TBAR + t)*DECD + j] = hn;
        __syncthreads();
    }
}

// ---------------- decoder LSTM + output linear + softmax ----------------
__global__ void __launch_bounds__(256) decoder_kernel(
    const float* __restrict__ x, const float* __restrict__ h0in, const float* __restrict__ c0in,
    const float* __restrict__ Wih, const float* __restrict__ Whh, const float* __restrict__ bias,
    const float* __restrict__ Wlin, const float* __restrict__ blin,
    float* __restrict__ notes)
{
    extern __shared__ float smd[];
    float* sWi = smd;
    float* sWh = sWi + 128*93;
    float* sb  = sWh + 128*33;
    float* sWl = sb + 128;
    float* sbl = sWl + 64*33;
    const int tid = threadIdx.x;
    for (int i=tid; i<128*93; i+=256) sWi[i] = Wih[i];
    for (int i=tid; i<128*32; i+=256){ int cc=i>>5, k=i&31; sWh[cc*33+k] = Whh[i]; }
    if (tid < 128) sb[tid] = bias[tid];
    for (int i=tid; i<64*32; i+=256){ int cc=i>>5, k=i&31; sWl[cc*33+k] = (cc<PP) ? Wlin[i] : 0.f; }
    if (tid < 64) sbl[tid] = (tid<PP) ? blin[tid] : 0.f;
    __syncthreads();

    const int w = tid>>5, lane = tid&31;
    const int row  = blockIdx.x*8 + w;
    const int bidx = row>>4, bar = row&15;
    float h = h0in[((size_t)bar*BB + bidx)*DECD + lane];
    float c = c0in[((size_t)bar*BB + bidx)*DECD + lane];
    const float emb = g_emb[(size_t)row*DECD + lane];
    const unsigned FULL = 0xffffffffu;
    const int c0_=lane, c1_=32+lane, c2_=64+lane, c3_=96+lane;

    for (int n=0;n<16;n++){
        const int time = bar*16 + n;
        float t0 = 0.f, t1 = 0.f;
        if (time > 0){
            const float* xr = x + ((size_t)bidx*TT + time-1)*PP;
            t0 = xr[lane];
            if (lane < 29) t1 = xr[32+lane];
        }
        float a0=sb[c0_], a1=sb[c1_], a2=sb[c2_], a3=sb[c3_];
        #pragma unroll
        for (int k=0;k<32;k++){
            float av = __shfl_sync(FULL, emb, k);
            a0 = fmaf(av, sWi[c0_*93+k], a0); a1 = fmaf(av, sWi[c1_*93+k], a1);
            a2 = fmaf(av, sWi[c2_*93+k], a2); a3 = fmaf(av, sWi[c3_*93+k], a3);
        }
        #pragma unroll
        for (int k=0;k<32;k++){
            float av = __shfl_sync(FULL, t0, k); const int kk=32+k;
            a0 = fmaf(av, sWi[c0_*93+kk], a0); a1 = fmaf(av, sWi[c1_*93+kk], a1);
            a2 = fmaf(av, sWi[c2_*93+kk], a2); a3 = fmaf(av, sWi[c3_*93+kk], a3);
        }
        #pragma unroll
        for (int k=0;k<29;k++){
            float av = __shfl_sync(FULL, t1, k); const int kk=64+k;
            a0 = fmaf(av, sWi[c0_*93+kk], a0); a1 = fmaf(av, sWi[c1_*93+kk], a1);
            a2 = fmaf(av, sWi[c2_*93+kk], a2); a3 = fmaf(av, sWi[c3_*93+kk], a3);
        }
        #pragma unroll
        for (int k=0;k<32;k++){
            float av = __shfl_sync(FULL, h, k);
            a0 = fmaf(av, sWh[c0_*33+k], a0); a1 = fmaf(av, sWh[c1_*33+k], a1);
            a2 = fmaf(av, sWh[c2_*33+k], a2); a3 = fmaf(av, sWh[c3_*33+k], a3);
        }
        float iv=sigmoidf_(a0), fv=sigmoidf_(a1), gv=tanhf(a2), ov=sigmoidf_(a3);
        c = fv*c + iv*gv;
        h = ov*tanhf(c);

        float l0 = sbl[lane], l1 = sbl[32+lane];
        #pragma unroll
        for (int k=0;k<32;k++){
            float hv = __shfl_sync(FULL, h, k);
            l0 = fmaf(hv, sWl[lane*33+k], l0);
            l1 = fmaf(hv, sWl[(32+lane)*33+k], l1);
        }
        float l1m = (lane < 29) ? l1 : -1e30f;
        float mx = fmaxf(l0, l1m);
        #pragma unroll
        for (int off=16; off; off>>=1) mx = fmaxf(mx, __shfl_xor_sync(FULL, mx, off));
        float e0 = __expf(l0 - mx);
        float e1 = (lane < 29) ? __expf(l1 - mx) : 0.f;
        float s = e0 + e1;
        #pragma unroll
        for (int off=16; off; off>>=1) s += __shfl_xor_sync(FULL, s, off);
        const float inv = 1.f/s;
        float* nr = notes + ((size_t)bidx*TT + time)*PP;
        nr[lane] = e0*inv;
        if (lane < 29) nr[32+lane] = e1*inv;
    }
}

// ---------------- launch ----------------
extern "C" void kernel_launch(void* const* d_in, const int* in_sizes, int n_in,
                              void* d_out, int out_size)
{
    const float* x        = (const float*)d_in[0];
    const float* eps      = (const float*)d_in[1];
    const float* dec_h0   = (const float*)d_in[2];
    const float* dec_c0   = (const float*)d_in[3];
    const float* eWih_f   = (const float*)d_in[4];
    const float* eWhh_f   = (const float*)d_in[5];
    const float* eb_f     = (const float*)d_in[6];
    const float* eWih_b   = (const float*)d_in[7];
    const float* eWhh_b   = (const float*)d_in[8];
    const float* eb_b     = (const float*)d_in[9];
    const float* Wout     = (const float*)d_in[10];
    const float* bout     = (const float*)d_in[11];
    const float* Wz       = (const float*)d_in[12];
    const float* bz       = (const float*)d_in[13];
    const float* conWih   = (const float*)d_in[14];
    const float* conWhh   = (const float*)d_in[15];
    const float* conb     = (const float*)d_in[16];
    const float* dWih     = (const float*)d_in[17];
    const float* dWhh     = (const float*)d_in[18];
    const float* db       = (const float*)d_in[19];
    const float* Wlin     = (const float*)d_in[20];
    const float* blin     = (const float*)d_in[21];

    float* out   = (float*)d_out;
    float* notes = out;
    float* zout  = out + (size_t)NROWS*PP;
    float* muo   = zout + (size_t)NROWS*DECD;
    float* lvo   = muo  + (size_t)NROWS*LATD;

    enc_persist_kernel<<<NBLK, 256>>>(x, eWih_f, eWhh_f, eb_f,
                                      eWih_b, eWhh_b, eb_b);

    cudaFuncSetAttribute(encout_mma_kernel, cudaFuncAttributeMaxDynamicSharedMemorySize, EO_SMEM);
    encout_mma_kernel<<<dim3(4, NROWS/128), 512, EO_SMEM>>>(Wout, bout, muo, lvo);

    zproj_kernel<<<NROWS/128, 256>>>(muo, lvo, eps, Wz, bz, zout);

    conductor_kernel<<<BB/8, 256>>>(zout, conWih, conWhh, conb);

    cudaFuncSetAttribute(decoder_kernel, cudaFuncAttributeMaxDynamicSharedMemorySize, 73728);
    decoder_kernel<<<(BB*TBAR)/8, 256, 73728>>>(x, dec_h0, dec_c0,
                                                dWih, dWhh, db, Wlin, blin, notes);
}

// round 5
// speedup vs baseline: 1.1687x; 1.1687x over previous
#include <cuda_runtime.h>
#include <math.h>
#include <stdint.h>

#define BB   512
#define TT   256
#define PP   61
#define HE   256
#define LATD 512
#define DECD 32
#define TBAR 16
#define NROWS (BB*TT)   // 131072
#define NBLK 128

// ---------------- scratch ----------------
__device__ float g_enc[(size_t)NROWS*512];          // (B*T, 2H)
__device__ float g_xp[(size_t)2*TT*1024*BB];        // [dir][pos][n(1024)][b] = x@Wih.T + b
__device__ float g_h[2*2*HE*BB];                    // [dir][parity][j][b]
__device__ float g_emb[(size_t)BB*TBAR*DECD];

// per-group barriers: group = (dir,bt), 16 groups of 8 blocks
__device__ unsigned g_cnt[16];
__device__ volatile unsigned g_sns[16];

typedef unsigned long long u64;

__device__ __forceinline__ float sigmoidf_(float v){ return 1.f/(1.f+__expf(-v)); }
__device__ __forceinline__ float tanh_ap(float v){
    float r; asm("tanh.approx.f32 %0, %1;" : "=f"(r) : "f"(v)); return r;
}
__device__ __forceinline__ u64 pk2(float lo, float hi){
    u64 r; asm("mov.b64 %0, {%1,%2};" : "=l"(r) : "f"(lo), "f"(hi)); return r;
}
__device__ __forceinline__ void upk2(u64 v, float &lo, float &hi){
    asm("mov.b64 {%0,%1}, %2;" : "=f"(lo), "=f"(hi) : "l"(v));
}
__device__ __forceinline__ void ffma2(u64 &d, u64 a, u64 b){
    asm("fma.rn.f32x2 %0, %1, %2, %0;" : "+l"(d) : "l"(a), "l"(b));
}

// ---------------- xproj: g_xp[dir][pos][n][b] = bias[n] + sum_k Wih[n][k]*x[b][pos][k] ----------------
// grid (32, 256, 2): bx -> ntile(8)*btile(4); by = pos; bz = dir. 256 thr, tile 128n x 128b, K=61
__global__ void __launch_bounds__(256) xproj_kernel(
    const float* __restrict__ x,
    const float* __restrict__ Wih_f, const float* __restrict__ b_f,
    const float* __restrict__ Wih_b, const float* __restrict__ b_b)
{
    extern __shared__ float sxp[];
    float* sWt = sxp;            // [k][n] 61 x 132
    float* sXt = sxp + 61*132;   // [k][b] 61 x 132
    const int n0  = (blockIdx.x >> 2)*128;
    const int b0  = (blockIdx.x & 3)*128;
    const int pos = blockIdx.y;
    const int dir = blockIdx.z;
    const float* Wih  = dir ? Wih_b : Wih_f;
    const float* bias = dir ? b_b   : b_f;
    const int tid = threadIdx.x, tx = tid&15, ty = tid>>4;

    {   // stage W tile and x tile (k-major)
        const int row = tid >> 1, ks = (tid & 1)*32;
        const float* wsrc = Wih + (size_t)(n0+row)*PP;
        const float* xsrc = x + ((size_t)(b0+row)*TT + pos)*PP;
        #pragma unroll
        for (int i=0;i<32;i++){
            int k = ks + i;
            if (k < PP){
                sWt[k*132 + row] = __ldg(wsrc + k);
                sXt[k*132 + row] = __ldg(xsrc + k);
            }
        }
    }
    __syncthreads();

    u64 acc[8][4];
    #pragma unroll
    for (int r=0;r<8;r++)
        #pragma unroll
        for (int c=0;c<4;c++) acc[r][c] = 0ull;

    for (int k=0;k<PP;k++){
        float4 a0 = *(const float4*)&sWt[k*132 + ty*8];
        float4 a1 = *(const float4*)&sWt[k*132 + ty*8 + 4];
        ulonglong2 b0v = *(const ulonglong2*)&sXt[k*132 + tx*8];
        ulonglong2 b1v = *(const ulonglong2*)&sXt[k*132 + tx*8 + 4];
        u64 bd[4] = { b0v.x, b0v.y, b1v.x, b1v.y };
        u64 ad[8] = { pk2(a0.x,a0.x), pk2(a0.y,a0.y), pk2(a0.z,a0.z), pk2(a0.w,a0.w),
                      pk2(a1.x,a1.x), pk2(a1.y,a1.y), pk2(a1.z,a1.z), pk2(a1.w,a1.w) };
        #pragma unroll
        for (int r=0;r<8;r++)
            #pragma unroll
            for (int c=0;c<4;c++) ffma2(acc[r][c], ad[r], bd[c]);
    }

    #pragma unroll
    for (int r=0;r<8;r++){
        const int n = n0 + ty*8 + r;
        const float bv = __ldg(bias + n);
        float* orow = g_xp + (((size_t)dir*TT + pos)*1024 + n)*BB + b0 + tx*8;
        float4 w0, w1;
        upk2(acc[r][0], w0.x, w0.y); upk2(acc[r][1], w0.z, w0.w);
        upk2(acc[r][2], w1.x, w1.y); upk2(acc[r][3], w1.z, w1.w);
        w0.x+=bv; w0.y+=bv; w0.z+=bv; w0.w+=bv;
        w1.x+=bv; w1.y+=bv; w1.z+=bv; w1.w+=bv;
        *(float4*)orow = w0;
        *(float4*)(orow+4) = w1;
    }
}

// ---------------- persistent bidirectional encoder, K=256, W-resident smem ----------------
// 128 blocks x 512 threads; block: dir(1)|bt(3)|nt(3); tile 64 rows x 128 gate-cols
// smem: Wsm [kp(128)][c*2+par] 32768 f (128KB), hb [kp][row*2+par] 16384 f (64KB)
#define ENC_SMEM ((32768+16384)*4)
__global__ void __launch_bounds__(512, 1) enc_persist_kernel(
    const float* __restrict__ Whh_f, const float* __restrict__ Whh_b)
{
    extern __shared__ float sme[];
    float* Wsm = sme;
    float* hb  = sme + 32768;
    __shared__ unsigned s_sense;

    const int bid = blockIdx.x;
    const int dir = bid >> 6;
    const int bt  = (bid >> 3) & 7;
    const int nt  = bid & 7;
    const int b0 = bt*64, j0 = nt*32;
    const int grp = bid >> 3;
    const float* Whh = dir ? Whh_b : Whh_f;

    const int tid = threadIdx.x;
    if (tid == 0) s_sense = g_sns[grp];

    // one-time: W into interleaved smem
    for (int u = tid; u < 128*64; u += 512){
        const int c = u & 127, kq = u >> 7;        // k = 4kq..4kq+3
        const int wrow = (c>>5)*HE + j0 + (c&31);
        float4 w = __ldg((const float4*)(Whh + (size_t)wrow*HE + 4*kq));
        *(u64*)&Wsm[(2*kq  )*256 + 2*c] = pk2(w.x, w.y);
        *(u64*)&Wsm[(2*kq+1)*256 + 2*c] = pk2(w.z, w.w);
    }
    // zero h parity 0 (owned slice: j0..j0+31, b0..b0+63)
    for (int i = tid; i < 32*64; i += 512){
        const int j = j0 + (i & 31), r = i >> 5;
        g_h[((dir*2+0)*HE + j)*BB + b0 + r] = 0.f;
    }

#define GRID_BAR() do {                                            \
        __threadfence();                                           \
        __syncthreads();                                           \
        if (tid == 0){                                             \
            unsigned my = s_sense;                                 \
            unsigned old = atomicAdd(&g_cnt[grp], 1u);             \
            if (old == 7u){                                        \
                g_cnt[grp] = 0;                                    \
                __threadfence();                                   \
                g_sns[grp] = my ^ 1u;                              \
            } else {                                               \
                while (g_sns[grp] == my) __nanosleep(32);          \
            }                                                      \
            s_sense = my ^ 1u;                                     \
        }                                                          \
        __syncthreads();                                           \
    } while(0)

    GRID_BAR();

    const int tx = tid & 31;        // j within tile
    const int ty = tid >> 5;        // 0..15, rows ty*4..+3
    const int jj = j0 + tx;

    float creg[4] = {0.f, 0.f, 0.f, 0.f};

    for (int t=0; t<TT; t++){
        const int tpos = dir ? (TT-1-t) : t;
        const int par = t & 1, parn = par ^ 1;

        // load h tile (64 rows x 256 k) into interleaved smem, via L2
        const float* hsrc = g_h + ((size_t)(dir*2+par)*HE)*BB;
        #pragma unroll
        for (int uu = 0; uu < 4; uu++){
            const int u = uu*512 + tid;
            const int kp = u >> 4, rq = u & 15;
            float4 e = __ldcg((const float4*)(hsrc + (size_t)(2*kp  )*BB + b0 + rq*4));
            float4 o = __ldcg((const float4*)(hsrc + (size_t)(2*kp+1)*BB + b0 + rq*4));
            float* d = hb + kp*128 + rq*8;
            *(float4*)(d)   = make_float4(e.x, o.x, e.y, o.y);
            *(float4*)(d+4) = make_float4(e.z, o.z, e.w, o.w);
        }

        // init acc from xp (lo = xp, hi = 0)
        u64 acc[4][4];
        const float* xpb = g_xp + ((size_t)dir*TT + tpos)*1024*BB;
        #pragma unroll
        for (int g=0; g<4; g++){
            float4 v = __ldg((const float4*)(xpb + (size_t)(g*HE + jj)*BB + b0 + ty*4));
            acc[0][g] = pk2(v.x, 0.f);
            acc[1][g] = pk2(v.y, 0.f);
            acc[2][g] = pk2(v.z, 0.f);
            acc[3][g] = pk2(v.w, 0.f);
        }
        __syncthreads();

        // main loop: K=256 as 128 k-pairs
        #pragma unroll 2
        for (int kp=0; kp<128; kp++){
            const ulonglong2 a01 = *(const ulonglong2*)&hb[kp*128 + ty*8];
            const ulonglong2 a23 = *(const ulonglong2*)&hb[kp*128 + ty*8 + 4];
            const u64 ap[4] = { a01.x, a01.y, a23.x, a23.y };
            u64 bd[4];
            #pragma unroll
            for (int g=0;g<4;g++) bd[g] = *(const u64*)&Wsm[kp*256 + (g*32+tx)*2];
            #pragma unroll
            for (int p=0;p<4;p++)
                #pragma unroll
                for (int g=0;g<4;g++) ffma2(acc[p][g], ap[p], bd[g]);
        }

        // epilogue: LSTM cell for 4 rows
        float hv[4];
        #pragma unroll
        for (int p=0;p<4;p++){
            float l0,h0,l1,h1,l2,h2,l3,h3;
            upk2(acc[p][0], l0, h0);
            upk2(acc[p][1], l1, h1);
            upk2(acc[p][2], l2, h2);
            upk2(acc[p][3], l3, h3);
            float iv = sigmoidf_(l0+h0);
            float fv = sigmoidf_(l1+h1);
            float gv = tanh_ap  (l2+h2);
            float ov = sigmoidf_(l3+h3);
            float cn = fv*creg[p] + iv*gv;
            creg[p] = cn;
            hv[p] = ov*tanh_ap(cn);
            const int gb = b0 + ty*4 + p;
            g_enc[((size_t)gb*TT + tpos)*512 + dir*HE + jj] = hv[p];
        }
        *(float4*)(g_h + ((size_t)(dir*2+parn)*HE + jj)*BB + b0 + ty*4) =
            make_float4(hv[0], hv[1], hv[2], hv[3]);

        GRID_BAR();
    }
#undef GRID_BAR
}

// ---------------- encoderOut GEMM (R2 known-good f32x2 SGEMM) ----------------
__global__ void __launch_bounds__(256) encout_kernel(
    const float* __restrict__ Wout, const float* __restrict__ bout,
    float* __restrict__ mu_out, float* __restrict__ lv_out)
{
    const int n0 = blockIdx.x*128, r0 = blockIdx.y*128;
    __shared__ float sA[8*132], sB[8*132];
    const int tid = threadIdx.x, tx = tid&15, ty = tid>>4;
    const int m = tid>>1, kb = (tid&1)*4;
    const float* arow = g_enc + (size_t)(r0+m)*512;
    const float* brow = Wout  + (size_t)(n0+m)*512;

    u64 acc[4][8];
    #pragma unroll
    for (int p=0;p<4;p++)
        #pragma unroll
        for (int c=0;c<8;c++) acc[p][c] = 0ull;

    float4 ra, rb;
    auto fetch = [&](int k0){
        ra = *(const float4*)&arow[k0+kb];
        rb = *(const float4*)&brow[k0+kb];
    };
    fetch(0);
    for (int ch=0; ch<64; ch++){
        __syncthreads();
        sA[(kb+0)*132+m]=ra.x; sA[(kb+1)*132+m]=ra.y; sA[(kb+2)*132+m]=ra.z; sA[(kb+3)*132+m]=ra.w;
        sB[(kb+0)*132+m]=rb.x; sB[(kb+1)*132+m]=rb.y; sB[(kb+2)*132+m]=rb.z; sB[(kb+3)*132+m]=rb.w;
        __syncthreads();
        if (ch<63) fetch((ch+1)*8);
        #pragma unroll
        for (int kk=0;kk<8;kk++){
            float4 a0 = *(const float4*)&sA[kk*132 + ty*8];
            float4 a1 = *(const float4*)&sA[kk*132 + ty*8 + 4];
            float4 b0 = *(const float4*)&sB[kk*132 + tx*8];
            float4 b1 = *(const float4*)&sB[kk*132 + tx*8 + 4];
            u64 ap[4] = { pk2(a0.x,a0.y), pk2(a0.z,a0.w),
                          pk2(a1.x,a1.y), pk2(a1.z,a1.w) };
            u64 bd[8] = { pk2(b0.x,b0.x), pk2(b0.y,b0.y), pk2(b0.z,b0.z), pk2(b0.w,b0.w),
                          pk2(b1.x,b1.x), pk2(b1.y,b1.y), pk2(b1.z,b1.z), pk2(b1.w,b1.w) };
            #pragma unroll
            for (int p=0;p<4;p++)
                #pragma unroll
                for (int c=0;c<8;c++) ffma2(acc[p][c], ap[p], bd[c]);
        }
    }
    #pragma unroll
    for (int p=0;p<4;p++){
        #pragma unroll
        for (int ci=0;ci<8;ci++){
            float lo, hi;
            upk2(acc[p][ci], lo, hi);
            const int col = n0 + tx*8 + ci;
            const float bv = bout[col];
            #pragma unroll
            for (int hh=0;hh<2;hh++){
                const size_t r = r0 + ty*8 + 2*p + hh;
                float v = (hh ? hi : lo) + bv;
                if (col < LATD) mu_out[r*LATD + col] = v;
                else {
                    float sp = (v > 20.f) ? v : log1pf(__expf(v));
                    lv_out[r*LATD + (col-LATD)] = sp;
                }
            }
        }
    }
}

// ---------------- z projection ----------------
__global__ void __launch_bounds__(256) zproj_kernel(
    const float* __restrict__ mu, const float* __restrict__ lv, const float* __restrict__ eps,
    const float* __restrict__ Wz, const float* __restrict__ bz, float* __restrict__ zout)
{
    const int r0 = blockIdx.x*128;
    __shared__ float sA[8*132], sB[8*33];
    const int tid = threadIdx.x, tx = tid&15, ty = tid>>4;
    const int m = tid>>1, kb = (tid&1)*4;
    const size_t rr = (size_t)r0 + m;
    const int bidx = (int)(rr >> 8);
    const float* murow  = mu  + rr*LATD;
    const float* lvrow  = lv  + rr*LATD;
    const float* epsrow = eps + (size_t)bidx*LATD;
    const int bnn = tid>>3, bkk = tid&7;

    float acc[8][2] = {};
    float ra[4], rb;
    auto fetch = [&](int k0){
        float4 m4 = *(const float4*)&murow[k0+kb];
        float4 l4 = *(const float4*)&lvrow[k0+kb];
        float4 e4 = *(const float4*)&epsrow[k0+kb];
        ra[0] = m4.x + e4.x*__expf(2.f*l4.x);
        ra[1] = m4.y + e4.y*__expf(2.f*l4.y);
        ra[2] = m4.z + e4.z*__expf(2.f*l4.z);
        ra[3] = m4.w + e4.w*__expf(2.f*l4.w);
        rb = Wz[(size_t)bnn*LATD + k0 + bkk];
    };
    fetch(0);
    for (int ch=0; ch<64; ch++){
        __syncthreads();
        #pragma unroll
        for (int i=0;i<4;i++) sA[(kb+i)*132+m] = ra[i];
        sB[bkk*33 + bnn] = rb;
        __syncthreads();
        if (ch<63) fetch((ch+1)*8);
        #pragma unroll
        for (int kk=0;kk<8;kk++){
            float4 a0 = *(const float4*)&sA[kk*132 + ty*8];
            float4 a1 = *(const float4*)&sA[kk*132 + ty*8 + 4];
            float a[8] = {a0.x,a0.y,a0.z,a0.w,a1.x,a1.y,a1.z,a1.w};
            float bv0 = sB[kk*33 + tx*2 + 0];
            float bv1 = sB[kk*33 + tx*2 + 1];
            #pragma unroll
            for (int r=0;r<8;r++){
                acc[r][0] = fmaf(a[r], bv0, acc[r][0]);
                acc[r][1] = fmaf(a[r], bv1, acc[r][1]);
            }
        }
    }
    #pragma unroll
    for (int ri=0;ri<8;ri++){
        const size_t r = r0 + ty*8 + ri;
        #pragma unroll
        for (int ci=0;ci<2;ci++){
            const int col = tx*2 + ci;
            zout[r*DECD + col] = acc[ri][ci] + bz[col];
        }
    }
}

// ---------------- conductor LSTM ----------------
__global__ void __launch_bounds__(256) conductor_kernel(
    const float* __restrict__ zout, const float* __restrict__ Wih,
    const float* __restrict__ Whh, const float* __restrict__ bias)
{
    __shared__ float sWi[128*33], sWh[128*33], sb[128];
    __shared__ float sh[8*33], sc[8*33], sz[8*33];
    const int tid = threadIdx.x;
    const int b0 = blockIdx.x*8;
    for (int i=tid; i<128*32; i+=256){ int cc=i>>5, k=i&31; sWi[cc*33+k]=Wih[i]; sWh[cc*33+k]=Whh[i]; }
    if (tid < 128) sb[tid] = bias[tid];
    { int mm=tid>>5, k=tid&31; sh[mm*33+k]=0.f; sc[mm*33+k]=0.f; }
    __syncthreads();

    const int j  = tid & 31;
    const int m  = tid >> 5;
    for (int t=0; t<TBAR; t++){
        { int mm=tid>>5, k=tid&31;
          sz[mm*33+k] = zout[((size_t)(b0+mm)*TT + t)*DECD + k]; }
        __syncthreads();
        float a0=sb[j], a1=sb[32+j], a2=sb[64+j], a3=sb[96+j];
        #pragma unroll
        for (int k=0;k<32;k++){
            float zv = sz[m*33+k], hv = sh[m*33+k];
            a0 += zv*sWi[( j   )*33+k] + hv*sWh[( j   )*33+k];
            a1 += zv*sWi[(32+j)*33+k]  + hv*sWh[(32+j)*33+k];
            a2 += zv*sWi[(64+j)*33+k]  + hv*sWh[(64+j)*33+k];
            a3 += zv*sWi[(96+j)*33+k]  + hv*sWh[(96+j)*33+k];
        }
        float iv=sigmoidf_(a0), fv=sigmoidf_(a1), gv=tanhf(a2), ov=sigmoidf_(a3);
        float cn = fv*sc[m*33+j] + iv*gv;
        float hn = ov*tanhf(cn);
        __syncthreads();
        sh[m*33+j]=hn; sc[m*33+j]=cn;
        g_emb[((size_t)(b0+m)*TBAR + t)*DECD + j] = hn;
        __syncthreads();
    }
}

// ---------------- decoder LSTM + output linear + softmax ----------------
__global__ void __launch_bounds__(256) decoder_kernel(
    const float* __restrict__ x, const float* __restrict__ h0in, const float* __restrict__ c0in,
    const float* __restrict__ Wih, const float* __restrict__ Whh, const float* __restrict__ bias,
    const float* __restrict__ Wlin, const float* __restrict__ blin,
    float* __restrict__ notes)
{
    extern __shared__ float smd[];
    float* sWi = smd;
    float* sWh = sWi + 128*93;
    float* sb  = sWh + 128*33;
    float* sWl = sb + 128;
    float* sbl = sWl + 64*33;
    const int tid = threadIdx.x;
    for (int i=tid; i<128*93; i+=256) sWi[i] = Wih[i];
    for (int i=tid; i<128*32; i+=256){ int cc=i>>5, k=i&31; sWh[cc*33+k] = Whh[i]; }
    if (tid < 128) sb[tid] = bias[tid];
    for (int i=tid; i<64*32; i+=256){ int cc=i>>5, k=i&31; sWl[cc*33+k] = (cc<PP) ? Wlin[i] : 0.f; }
    if (tid < 64) sbl[tid] = (tid<PP) ? blin[tid] : 0.f;
    __syncthreads();

    const int w = tid>>5, lane = tid&31;
    const int row  = blockIdx.x*8 + w;
    const int bidx = row>>4, bar = row&15;
    float h = h0in[((size_t)bar*BB + bidx)*DECD + lane];
    float c = c0in[((size_t)bar*BB + bidx)*DECD + lane];
    const float emb = g_emb[(size_t)row*DECD + lane];
    const unsigned FULL = 0xffffffffu;
    const int c0_=lane, c1_=32+lane, c2_=64+lane, c3_=96+lane;

    for (int n=0;n<16;n++){
        const int time = bar*16 + n;
        float t0 = 0.f, t1 = 0.f;
        if (time > 0){
            const float* xr = x + ((size_t)bidx*TT + time-1)*PP;
            t0 = xr[lane];
            if (lane < 29) t1 = xr[32+lane];
        }
        float a0=sb[c0_], a1=sb[c1_], a2=sb[c2_], a3=sb[c3_];
        #pragma unroll
        for (int k=0;k<32;k++){
            float av = __shfl_sync(FULL, emb, k);
            a0 = fmaf(av, sWi[c0_*93+k], a0); a1 = fmaf(av, sWi[c1_*93+k], a1);
            a2 = fmaf(av, sWi[c2_*93+k], a2); a3 = fmaf(av, sWi[c3_*93+k], a3);
        }
        #pragma unroll
        for (int k=0;k<32;k++){
            float av = __shfl_sync(FULL, t0, k); const int kk=32+k;
            a0 = fmaf(av, sWi[c0_*93+kk], a0); a1 = fmaf(av, sWi[c1_*93+kk], a1);
            a2 = fmaf(av, sWi[c2_*93+kk], a2); a3 = fmaf(av, sWi[c3_*93+kk], a3);
        }
        #pragma unroll
        for (int k=0;k<29;k++){
            float av = __shfl_sync(FULL, t1, k); const int kk=64+k;
            a0 = fmaf(av, sWi[c0_*93+kk], a0); a1 = fmaf(av, sWi[c1_*93+kk], a1);
            a2 = fmaf(av, sWi[c2_*93+kk], a2); a3 = fmaf(av, sWi[c3_*93+kk], a3);
        }
        #pragma unroll
        for (int k=0;k<32;k++){
            float av = __shfl_sync(FULL, h, k);
            a0 = fmaf(av, sWh[c0_*33+k], a0); a1 = fmaf(av, sWh[c1_*33+k], a1);
            a2 = fmaf(av, sWh[c2_*33+k], a2); a3 = fmaf(av, sWh[c3_*33+k], a3);
        }
        float iv=sigmoidf_(a0), fv=sigmoidf_(a1), gv=tanhf(a2), ov=sigmoidf_(a3);
        c = fv*c + iv*gv;
        h = ov*tanhf(c);

        float l0 = sbl[lane], l1 = sbl[32+lane];
        #pragma unroll
        for (int k=0;k<32;k++){
            float hv = __shfl_sync(FULL, h, k);
            l0 = fmaf(hv, sWl[lane*33+k], l0);
            l1 = fmaf(hv, sWl[(32+lane)*33+k], l1);
        }
        float l1m = (lane < 29) ? l1 : -1e30f;
        float mx = fmaxf(l0, l1m);
        #pragma unroll
        for (int off=16; off; off>>=1) mx = fmaxf(mx, __shfl_xor_sync(FULL, mx, off));
        float e0 = __expf(l0 - mx);
        float e1 = (lane < 29) ? __expf(l1 - mx) : 0.f;
        float s = e0 + e1;
        #pragma unroll
        for (int off=16; off; off>>=1) s += __shfl_xor_sync(FULL, s, off);
        const float inv = 1.f/s;
        float* nr = notes + ((size_t)bidx*TT + time)*PP;
        nr[lane] = e0*inv;
        if (lane < 29) nr[32+lane] = e1*inv;
    }
}

// ---------------- launch ----------------
extern "C" void kernel_launch(void* const* d_in, const int* in_sizes, int n_in,
                              void* d_out, int out_size)
{
    const float* x        = (const float*)d_in[0];
    const float* eps      = (const float*)d_in[1];
    const float* dec_h0   = (const float*)d_in[2];
    const float* dec_c0   = (const float*)d_in[3];
    const float* eWih_f   = (const float*)d_in[4];
    const float* eWhh_f   = (const float*)d_in[5];
    const float* eb_f     = (const float*)d_in[6];
    const float* eWih_b   = (const float*)d_in[7];
    const float* eWhh_b   = (const float*)d_in[8];
    const float* eb_b     = (const float*)d_in[9];
    const float* Wout     = (const float*)d_in[10];
    const float* bout     = (const float*)d_in[11];
    const float* Wz       = (const float*)d_in[12];
    const float* bz       = (const float*)d_in[13];
    const float* conWih   = (const float*)d_in[14];
    const float* conWhh   = (const float*)d_in[15];
    const float* conb     = (const float*)d_in[16];
    const float* dWih     = (const float*)d_in[17];
    const float* dWhh     = (const float*)d_in[18];
    const float* db       = (const float*)d_in[19];
    const float* Wlin     = (const float*)d_in[20];
    const float* blin     = (const float*)d_in[21];

    float* out   = (float*)d_out;
    float* notes = out;
    float* zout  = out + (size_t)NROWS*PP;
    float* muo   = zout + (size_t)NROWS*DECD;
    float* lvo   = muo  + (size_t)NROWS*LATD;

    cudaFuncSetAttribute(xproj_kernel, cudaFuncAttributeMaxDynamicSharedMemorySize, 66048);
    xproj_kernel<<<dim3(32, TT, 2), 256, 66048>>>(x, eWih_f, eb_f, eWih_b, eb_b);

    cudaFuncSetAttribute(enc_persist_kernel, cudaFuncAttributeMaxDynamicSharedMemorySize, ENC_SMEM);
    enc_persist_kernel<<<NBLK, 512, ENC_SMEM>>>(eWhh_f, eWhh_b);

    encout_kernel<<<dim3(8, NROWS/128), 256>>>(Wout, bout, muo, lvo);

    zproj_kernel<<<NROWS/128, 256>>>(muo, lvo, eps, Wz, bz, zout);

    conductor_kernel<<<BB/8, 256>>>(zout, conWih, conWhh, conb);

    cudaFuncSetAttribute(decoder_kernel, cudaFuncAttributeMaxDynamicSharedMemorySize, 73728);
    decoder_kernel<<<(BB*TBAR)/8, 256, 73728>>>(x, dec_h0, dec_c0,
                                                dWih, dWhh, db, Wlin, blin, notes);
}

// round 6
// speedup vs baseline: 1.2622x; 1.0800x over previous
#include <cuda_runtime.h>
#include <math.h>
#include <stdint.h>

#define BB   512
#define TT   256
#define PP   61
#define HE   256
#define LATD 512
#define DECD 32
#define TBAR 16
#define NROWS (BB*TT)   // 131072
#define NBLK 128

// ---------------- scratch ----------------
__device__ float g_enc[(size_t)NROWS*512];          // (B*T, 2H)
__device__ float g_xp[(size_t)2*TT*1024*BB];        // [dir][pos][n][b]
__device__ float g_h[2*2*HE*BB];                    // [dir][parity][j][b]
__device__ float g_emb[(size_t)BB*TBAR*DECD];

__device__ unsigned g_cnt[16];
__device__ volatile unsigned g_sns[16];

typedef unsigned long long u64;

__device__ __forceinline__ float sigmoidf_(float v){ return 1.f/(1.f+__expf(-v)); }
__device__ __forceinline__ float tanh_ap(float v){
    float r; asm("tanh.approx.f32 %0, %1;" : "=f"(r) : "f"(v)); return r;
}
__device__ __forceinline__ u64 pk2(float lo, float hi){
    u64 r; asm("mov.b64 %0, {%1,%2};" : "=l"(r) : "f"(lo), "f"(hi)); return r;
}
__device__ __forceinline__ void upk2(u64 v, float &lo, float &hi){
    asm("mov.b64 {%0,%1}, %2;" : "=f"(lo), "=f"(hi) : "l"(v));
}
__device__ __forceinline__ void ffma2(u64 &d, u64 a, u64 b){
    asm("fma.rn.f32x2 %0, %1, %2, %0;" : "+l"(d) : "l"(a), "l"(b));
}
__device__ __forceinline__ void mma8(float &d0, float &d1, float &d2, float &d3,
    uint32_t a0, uint32_t a1, uint32_t a2, uint32_t a3, uint32_t b0, uint32_t b1){
    asm volatile("mma.sync.aligned.m16n8k8.row.col.f32.tf32.tf32.f32 "
        "{%0,%1,%2,%3},{%4,%5,%6,%7},{%8,%9},{%0,%1,%2,%3};"
        : "+f"(d0),"+f"(d1),"+f"(d2),"+f"(d3)
        : "r"(a0),"r"(a1),"r"(a2),"r"(a3),"r"(b0),"r"(b1));
}

// ---------------- xproj (unchanged from R5) ----------------
__global__ void __launch_bounds__(256) xproj_kernel(
    const float* __restrict__ x,
    const float* __restrict__ Wih_f, const float* __restrict__ b_f,
    const float* __restrict__ Wih_b, const float* __restrict__ b_b)
{
    extern __shared__ float sxp[];
    float* sWt = sxp;
    float* sXt = sxp + 61*132;
    const int n0  = (blockIdx.x >> 2)*128;
    const int b0  = (blockIdx.x & 3)*128;
    const int pos = blockIdx.y;
    const int dir = blockIdx.z;
    const float* Wih  = dir ? Wih_b : Wih_f;
    const float* bias = dir ? b_b   : b_f;
    const int tid = threadIdx.x, tx = tid&15, ty = tid>>4;

    {
        const int row = tid >> 1, ks = (tid & 1)*32;
        const float* wsrc = Wih + (size_t)(n0+row)*PP;
        const float* xsrc = x + ((size_t)(b0+row)*TT + pos)*PP;
        #pragma unroll
        for (int i=0;i<32;i++){
            int k = ks + i;
            if (k < PP){
                sWt[k*132 + row] = __ldg(wsrc + k);
                sXt[k*132 + row] = __ldg(xsrc + k);
            }
        }
    }
    __syncthreads();

    u64 acc[8][4];
    #pragma unroll
    for (int r=0;r<8;r++)
        #pragma unroll
        for (int c=0;c<4;c++) acc[r][c] = 0ull;

    for (int k=0;k<PP;k++){
        float4 a0 = *(const float4*)&sWt[k*132 + ty*8];
        float4 a1 = *(const float4*)&sWt[k*132 + ty*8 + 4];
        ulonglong2 b0v = *(const ulonglong2*)&sXt[k*132 + tx*8];
        ulonglong2 b1v = *(const ulonglong2*)&sXt[k*132 + tx*8 + 4];
        u64 bd[4] = { b0v.x, b0v.y, b1v.x, b1v.y };
        u64 ad[8] = { pk2(a0.x,a0.x), pk2(a0.y,a0.y), pk2(a0.z,a0.z), pk2(a0.w,a0.w),
                      pk2(a1.x,a1.x), pk2(a1.y,a1.y), pk2(a1.z,a1.z), pk2(a1.w,a1.w) };
        #pragma unroll
        for (int r=0;r<8;r++)
            #pragma unroll
            for (int c=0;c<4;c++) ffma2(acc[r][c], ad[r], bd[c]);
    }

    #pragma unroll
    for (int r=0;r<8;r++){
        const int n = n0 + ty*8 + r;
        const float bv = __ldg(bias + n);
        float* orow = g_xp + (((size_t)dir*TT + pos)*1024 + n)*BB + b0 + tx*8;
        float4 w0, w1;
        upk2(acc[r][0], w0.x, w0.y); upk2(acc[r][1], w0.z, w0.w);
        upk2(acc[r][2], w1.x, w1.y); upk2(acc[r][3], w1.z, w1.w);
        w0.x+=bv; w0.y+=bv; w0.z+=bv; w0.w+=bv;
        w1.x+=bv; w1.y+=bv; w1.z+=bv; w1.w+=bv;
        *(float4*)orow = w0;
        *(float4*)(orow+4) = w1;
    }
}

// ---------------- persistent bidirectional encoder (unchanged from R5) ----------------
#define ENC_SMEM ((32768+16384)*4)
__global__ void __launch_bounds__(512, 1) enc_persist_kernel(
    const float* __restrict__ Whh_f, const float* __restrict__ Whh_b)
{
    extern __shared__ float sme[];
    float* Wsm = sme;
    float* hb  = sme + 32768;
    __shared__ unsigned s_sense;

    const int bid = blockIdx.x;
    const int dir = bid >> 6;
    const int bt  = (bid >> 3) & 7;
    const int nt  = bid & 7;
    const int b0 = bt*64, j0 = nt*32;
    const int grp = bid >> 3;
    const float* Whh = dir ? Whh_b : Whh_f;

    const int tid = threadIdx.x;
    if (tid == 0) s_sense = g_sns[grp];

    for (int u = tid; u < 128*64; u += 512){
        const int c = u & 127, kq = u >> 7;
        const int wrow = (c>>5)*HE + j0 + (c&31);
        float4 w = __ldg((const float4*)(Whh + (size_t)wrow*HE + 4*kq));
        *(u64*)&Wsm[(2*kq  )*256 + 2*c] = pk2(w.x, w.y);
        *(u64*)&Wsm[(2*kq+1)*256 + 2*c] = pk2(w.z, w.w);
    }
    for (int i = tid; i < 32*64; i += 512){
        const int j = j0 + (i & 31), r = i >> 5;
        g_h[((dir*2+0)*HE + j)*BB + b0 + r] = 0.f;
    }

#define GRID_BAR() do {                                            \
        __threadfence();                                           \
        __syncthreads();                                           \
        if (tid == 0){                                             \
            unsigned my = s_sense;                                 \
            unsigned old = atomicAdd(&g_cnt[grp], 1u);             \
            if (old == 7u){                                        \
                g_cnt[grp] = 0;                                    \
                __threadfence();                                   \
                g_sns[grp] = my ^ 1u;                              \
            } else {                                               \
                while (g_sns[grp] == my) __nanosleep(32);          \
            }                                                      \
            s_sense = my ^ 1u;                                     \
        }                                                          \
        __syncthreads();                                           \
    } while(0)

    GRID_BAR();

    const int tx = tid & 31;
    const int ty = tid >> 5;
    const int jj = j0 + tx;

    float creg[4] = {0.f, 0.f, 0.f, 0.f};

    for (int t=0; t<TT; t++){
        const int tpos = dir ? (TT-1-t) : t;
        const int par = t & 1, parn = par ^ 1;

        const float* hsrc = g_h + ((size_t)(dir*2+par)*HE)*BB;
        #pragma unroll
        for (int uu = 0; uu < 4; uu++){
            const int u = uu*512 + tid;
            const int kp = u >> 4, rq = u & 15;
            float4 e = __ldcg((const float4*)(hsrc + (size_t)(2*kp  )*BB + b0 + rq*4));
            float4 o = __ldcg((const float4*)(hsrc + (size_t)(2*kp+1)*BB + b0 + rq*4));
            float* d = hb + kp*128 + rq*8;
            *(float4*)(d)   = make_float4(e.x, o.x, e.y, o.y);
            *(float4*)(d+4) = make_float4(e.z, o.z, e.w, o.w);
        }

        u64 acc[4][4];
        const float* xpb = g_xp + ((size_t)dir*TT + tpos)*1024*BB;
        #pragma unroll
        for (int g=0; g<4; g++){
            float4 v = __ldg((const float4*)(xpb + (size_t)(g*HE + jj)*BB + b0 + ty*4));
            acc[0][g] = pk2(v.x, 0.f);
            acc[1][g] = pk2(v.y, 0.f);
            acc[2][g] = pk2(v.z, 0.f);
            acc[3][g] = pk2(v.w, 0.f);
        }
        __syncthreads();

        #pragma unroll 2
        for (int kp=0; kp<128; kp++){
            const ulonglong2 a01 = *(const ulonglong2*)&hb[kp*128 + ty*8];
            const ulonglong2 a23 = *(const ulonglong2*)&hb[kp*128 + ty*8 + 4];
            const u64 ap[4] = { a01.x, a01.y, a23.x, a23.y };
            u64 bd[4];
            #pragma unroll
            for (int g=0;g<4;g++) bd[g] = *(const u64*)&Wsm[kp*256 + (g*32+tx)*2];
            #pragma unroll
            for (int p=0;p<4;p++)
                #pragma unroll
                for (int g=0;g<4;g++) ffma2(acc[p][g], ap[p], bd[g]);
        }

        float hv[4];
        #pragma unroll
        for (int p=0;p<4;p++){
            float l0,h0,l1,h1,l2,h2,l3,h3;
            upk2(acc[p][0], l0, h0);
            upk2(acc[p][1], l1, h1);
            upk2(acc[p][2], l2, h2);
            upk2(acc[p][3], l3, h3);
            float iv = sigmoidf_(l0+h0);
            float fv = sigmoidf_(l1+h1);
            float gv = tanh_ap  (l2+h2);
            float ov = sigmoidf_(l3+h3);
            float cn = fv*creg[p] + iv*gv;
            creg[p] = cn;
            hv[p] = ov*tanh_ap(cn);
            const int gb = b0 + ty*4 + p;
            g_enc[((size_t)gb*TT + tpos)*512 + dir*HE + jj] = hv[p];
        }
        *(float4*)(g_h + ((size_t)(dir*2+parn)*HE + jj)*BB + b0 + ty*4) =
            make_float4(hv[0], hv[1], hv[2], hv[3]);

        GRID_BAR();
    }
#undef GRID_BAR
}

// ---------------- encoderOut: pre-split 3-pass tf32 mma.sync ----------------
// 256 thr / 8 warps (4m x 2n); tile M=128 x N=128; K=512 in 16 chunks of 32.
// smem stage: AHI|ALO|BHI|BLO each 128x36 floats (pad36 -> bank 4m+k distinct)
#define EO2_PAD  36
#define EO2_MAT  (128*EO2_PAD)          // 4608 floats
#define EO2_STG  (4*EO2_MAT)            // 18432 floats per stage
#define EO2_SMEM (2*EO2_STG*4)          // 147456 bytes

__global__ void __launch_bounds__(256,1) encout_mma_kernel(
    const float* __restrict__ Wout, const float* __restrict__ bout,
    float* __restrict__ mu_out, float* __restrict__ lv_out)
{
    extern __shared__ float sm[];
    const int tid = threadIdx.x, lane = tid & 31, wid = tid >> 5;
    const int wm = wid & 3, wn = wid >> 2;     // 4 m-quarters x 2 n-halves
    const int n0 = blockIdx.x*128, r0 = blockIdx.y*128;
    const int g = lane >> 2, t4 = lane & 3;

    float acc[2][8][4];
    #pragma unroll
    for (int a=0;a<2;a++)
        #pragma unroll
        for (int b=0;b<8;b++)
            #pragma unroll
            for (int c=0;c<4;c++) acc[a][b][c] = 0.f;

    // staging: each thread owns 4 A-float4 and 4 B-float4 per chunk
    const int srow = tid >> 1;                       // 0..127 (2 thr/row)
    const int sq   = (tid & 1)*4;                    // float4 pair: q = sq..sq+3
    const float* asrc = g_enc + (size_t)(r0+srow)*512 + sq*4;
    const float* bsrc = Wout  + (size_t)(n0+srow)*512 + sq*4;
    const int sdst = srow*EO2_PAD + sq*4;

    auto split_sts = [&](float* hi_base, float* lo_base, const float4* v){
        #pragma unroll
        for (int j=0;j<4;j++){
            float4 h, l;
            h.x = __uint_as_float(__float_as_uint(v[j].x) & 0xFFFFE000u); l.x = v[j].x - h.x;
            h.y = __uint_as_float(__float_as_uint(v[j].y) & 0xFFFFE000u); l.y = v[j].y - h.y;
            h.z = __uint_as_float(__float_as_uint(v[j].z) & 0xFFFFE000u); l.z = v[j].z - h.z;
            h.w = __uint_as_float(__float_as_uint(v[j].w) & 0xFFFFE000u); l.w = v[j].w - h.w;
            *(float4*)(hi_base + sdst + j*4) = h;     // only j<... sq covers q..q+3: j indexes q
            *(float4*)(lo_base + sdst + j*4) = l;
        }
    };

    float4 av[4], bv[4];
    #pragma unroll
    for (int j=0;j<4;j++){ av[j] = __ldg((const float4*)(asrc + j*16)); } // wrong stride? see below
    // NOTE: q positions are sq+j, element offset (sq+j)*4 floats = sdst covers via j*4; src offset j*16B? src is float*: (sq+j)*4 floats -> asrc already at sq*4, advance j*4 floats
    #pragma unroll
    for (int j=0;j<4;j++){ av[j] = __ldg((const float4*)(asrc + j*4)); bv[j] = __ldg((const float4*)(bsrc + j*4)); }
    split_sts(sm,            sm + EO2_MAT,   av);
    split_sts(sm + 2*EO2_MAT, sm + 3*EO2_MAT, bv);
    __syncthreads();

    for (int c=0;c<16;c++){
        if (c+1 < 16){
            #pragma unroll
            for (int j=0;j<4;j++){
                av[j] = __ldg((const float4*)(asrc + (c+1)*32 + j*4));
                bv[j] = __ldg((const float4*)(bsrc + (c+1)*32 + j*4));
            }
        }
        const float* AH = sm + (c&1)*EO2_STG;
        const float* AL = AH + EO2_MAT;
        const float* BH = AH + 2*EO2_MAT;
        const float* BL = AH + 3*EO2_MAT;

        #pragma unroll
        for (int kt=0;kt<4;kt++){
            const int kk = kt*8 + t4;
            uint32_t ah[2][4], al[2][4];
            #pragma unroll
            for (int mt=0;mt<2;mt++){
                const int r = wm*32 + mt*16 + g;
                ah[mt][0] = __float_as_uint(AH[ r    *EO2_PAD + kk]);
                ah[mt][1] = __float_as_uint(AH[(r+8) *EO2_PAD + kk]);
                ah[mt][2] = __float_as_uint(AH[ r    *EO2_PAD + kk + 4]);
                ah[mt][3] = __float_as_uint(AH[(r+8) *EO2_PAD + kk + 4]);
                al[mt][0] = __float_as_uint(AL[ r    *EO2_PAD + kk]);
                al[mt][1] = __float_as_uint(AL[(r+8) *EO2_PAD + kk]);
                al[mt][2] = __float_as_uint(AL[ r    *EO2_PAD + kk + 4]);
                al[mt][3] = __float_as_uint(AL[(r+8) *EO2_PAD + kk + 4]);
            }
            #pragma unroll
            for (int nt=0;nt<8;nt++){
                const int n = wn*64 + nt*8 + g;
                uint32_t bh0 = __float_as_uint(BH[n*EO2_PAD + kk]);
                uint32_t bh1 = __float_as_uint(BH[n*EO2_PAD + kk + 4]);
                uint32_t bl0 = __float_as_uint(BL[n*EO2_PAD + kk]);
                uint32_t bl1 = __float_as_uint(BL[n*EO2_PAD + kk + 4]);
                #pragma unroll
                for (int mt=0;mt<2;mt++){
                    mma8(acc[mt][nt][0],acc[mt][nt][1],acc[mt][nt][2],acc[mt][nt][3],
                         ah[mt][0],ah[mt][1],ah[mt][2],ah[mt][3], bh0,bh1);
                    mma8(acc[mt][nt][0],acc[mt][nt][1],acc[mt][nt][2],acc[mt][nt][3],
                         ah[mt][0],ah[mt][1],ah[mt][2],ah[mt][3], bl0,bl1);
                    mma8(acc[mt][nt][0],acc[mt][nt][1],acc[mt][nt][2],acc[mt][nt][3],
                         al[mt][0],al[mt][1],al[mt][2],al[mt][3], bh0,bh1);
                }
            }
        }
        if (c+1 < 16){
            float* NB = sm + ((c+1)&1)*EO2_STG;
            split_sts(NB,            NB + EO2_MAT,   av);
            split_sts(NB + 2*EO2_MAT, NB + 3*EO2_MAT, bv);
        }
        __syncthreads();
    }

    // epilogue: acc[mt][nt][{0,1}] -> row wm*32+mt*16+g, cols nt*8+t4*2(+1); [2,3] -> row+8
    #pragma unroll
    for (int mt=0;mt<2;mt++){
        const size_t row = (size_t)r0 + wm*32 + mt*16 + g;
        #pragma unroll
        for (int nt=0;nt<8;nt++){
            const int col = n0 + wn*64 + nt*8 + t4*2;
            const float bb0 = __ldg(bout + col), bb1 = __ldg(bout + col + 1);
            float v0 = acc[mt][nt][0] + bb0, v1 = acc[mt][nt][1] + bb1;
            float v2 = acc[mt][nt][2] + bb0, v3 = acc[mt][nt][3] + bb1;
            if (n0 < LATD){
                *(float2*)(mu_out + row*LATD + col)     = make_float2(v0, v1);
                *(float2*)(mu_out + (row+8)*LATD + col) = make_float2(v2, v3);
            } else {
                v0 = (v0>20.f)?v0:log1pf(__expf(v0));
                v1 = (v1>20.f)?v1:log1pf(__expf(v1));
                v2 = (v2>20.f)?v2:log1pf(__expf(v2));
                v3 = (v3>20.f)?v3:log1pf(__expf(v3));
                *(float2*)(lv_out + row*LATD + (col-LATD))     = make_float2(v0, v1);
                *(float2*)(lv_out + (row+8)*LATD + (col-LATD)) = make_float2(v2, v3);
            }
        }
    }
}

// ---------------- z projection (unchanged) ----------------
__global__ void __launch_bounds__(256) zproj_kernel(
    const float* __restrict__ mu, const float* __restrict__ lv, const float* __restrict__ eps,
    const float* __restrict__ Wz, const float* __restrict__ bz, float* __restrict__ zout)
{
    const int r0 = blockIdx.x*128;
    __shared__ float sA[8*132], sB[8*33];
    const int tid = threadIdx.x, tx = tid&15, ty = tid>>4;
    const int m = tid>>1, kb = (tid&1)*4;
    const size_t rr = (size_t)r0 + m;
    const int bidx = (int)(rr >> 8);
    const float* murow  = mu  + rr*LATD;
    const float* lvrow  = lv  + rr*LATD;
    const float* epsrow = eps + (size_t)bidx*LATD;
    const int bnn = tid>>3, bkk = tid&7;

    float acc[8][2] = {};
    float ra[4], rb;
    auto fetch = [&](int k0){
        float4 m4 = *(const float4*)&murow[k0+kb];
        float4 l4 = *(const float4*)&lvrow[k0+kb];
        float4 e4 = *(const float4*)&epsrow[k0+kb];
        ra[0] = m4.x + e4.x*__expf(2.f*l4.x);
        ra[1] = m4.y + e4.y*__expf(2.f*l4.y);
        ra[2] = m4.z + e4.z*__expf(2.f*l4.z);
        ra[3] = m4.w + e4.w*__expf(2.f*l4.w);
        rb = Wz[(size_t)bnn*LATD + k0 + bkk];
    };
    fetch(0);
    for (int ch=0; ch<64; ch++){
        __syncthreads();
        #pragma unroll
        for (int i=0;i<4;i++) sA[(kb+i)*132+m] = ra[i];
        sB[bkk*33 + bnn] = rb;
        __syncthreads();
        if (ch<63) fetch((ch+1)*8);
        #pragma unroll
        for (int kk=0;kk<8;kk++){
            float4 a0 = *(const float4*)&sA[kk*132 + ty*8];
            float4 a1 = *(const float4*)&sA[kk*132 + ty*8 + 4];
            float a[8] = {a0.x,a0.y,a0.z,a0.w,a1.x,a1.y,a1.z,a1.w};
            float bv0 = sB[kk*33 + tx*2 + 0];
            float bv1 = sB[kk*33 + tx*2 + 1];
            #pragma unroll
            for (int r=0;r<8;r++){
                acc[r][0] = fmaf(a[r], bv0, acc[r][0]);
                acc[r][1] = fmaf(a[r], bv1, acc[r][1]);
            }
        }
    }
    #pragma unroll
    for (int ri=0;ri<8;ri++){
        const size_t r = r0 + ty*8 + ri;
        #pragma unroll
        for (int ci=0;ci<2;ci++){
            const int col = tx*2 + ci;
            zout[r*DECD + col] = acc[ri][ci] + bz[col];
        }
    }
}

// ---------------- conductor LSTM (unchanged) ----------------
__global__ void __launch_bounds__(256) conductor_kernel(
    const float* __restrict__ zout, const float* __restrict__ Wih,
    const float* __restrict__ Whh, const float* __restrict__ bias)
{
    __shared__ float sWi[128*33], sWh[128*33], sb[128];
    __shared__ float sh[8*33], sc[8*33], sz[8*33];
    const int tid = threadIdx.x;
    const int b0 = blockIdx.x*8;
    for (int i=tid; i<128*32; i+=256){ int cc=i>>5, k=i&31; sWi[cc*33+k]=Wih[i]; sWh[cc*33+k]=Whh[i]; }
    if (tid < 128) sb[tid] = bias[tid];
    { int mm=tid>>5, k=tid&31; sh[mm*33+k]=0.f; sc[mm*33+k]=0.f; }
    __syncthreads();

    const int j  = tid & 31;
    const int m  = tid >> 5;
    for (int t=0; t<TBAR; t++){
        { int mm=tid>>5, k=tid&31;
          sz[mm*33+k] = zout[((size_t)(b0+mm)*TT + t)*DECD + k]; }
        __syncthreads();
        float a0=sb[j], a1=sb[32+j], a2=sb[64+j], a3=sb[96+j];
        #pragma unroll
        for (int k=0;k<32;k++){
            float zv = sz[m*33+k], hv = sh[m*33+k];
            a0 += zv*sWi[( j   )*33+k] + hv*sWh[( j   )*33+k];
            a1 += zv*sWi[(32+j)*33+k]  + hv*sWh[(32+j)*33+k];
            a2 += zv*sWi[(64+j)*33+k]  + hv*sWh[(64+j)*33+k];
            a3 += zv*sWi[(96+j)*33+k]  + hv*sWh[(96+j)*33+k];
        }
        float iv=sigmoidf_(a0), fv=sigmoidf_(a1), gv=tanhf(a2), ov=sigmoidf_(a3);
        float cn = fv*sc[m*33+j] + iv*gv;
        float hn = ov*tanhf(cn);
        __syncthreads();
        sh[m*33+j]=hn; sc[m*33+j]=cn;
        g_emb[((size_t)(b0+m)*TBAR + t)*DECD + j] = hn;
        __syncthreads();
    }
}

// ---------------- decoder (unchanged) ----------------
__global__ void __launch_bounds__(256) decoder_kernel(
    const float* __restrict__ x, const float* __restrict__ h0in, const float* __restrict__ c0in,
    const float* __restrict__ Wih, const float* __restrict__ Whh, const float* __restrict__ bias,
    const float* __restrict__ Wlin, const float* __restrict__ blin,
    float* __restrict__ notes)
{
    extern __shared__ float smd[];
    float* sWi = smd;
    float* sWh = sWi + 128*93;
    float* sb  = sWh + 128*33;
    float* sWl = sb + 128;
    float* sbl = sWl + 64*33;
    const int tid = threadIdx.x;
    for (int i=tid; i<128*93; i+=256) sWi[i] = Wih[i];
    for (int i=tid; i<128*32; i+=256){ int cc=i>>5, k=i&31; sWh[cc*33+k] = Whh[i]; }
    if (tid < 128) sb[tid] = bias[tid];
    for (int i=tid; i<64*32; i+=256){ int cc=i>>5, k=i&31; sWl[cc*33+k] = (cc<PP) ? Wlin[i] : 0.f; }
    if (tid < 64) sbl[tid] = (tid<PP) ? blin[tid] : 0.f;
    __syncthreads();

    const int w = tid>>5, lane = tid&31;
    const int row  = blockIdx.x*8 + w;
    const int bidx = row>>4, bar = row&15;
    float h = h0in[((size_t)bar*BB + bidx)*DECD + lane];
    float c = c0in[((size_t)bar*BB + bidx)*DECD + lane];
    const float emb = g_emb[(size_t)row*DECD + lane];
    const unsigned FULL = 0xffffffffu;
    const int c0_=lane, c1_=32+lane, c2_=64+lane, c3_=96+lane;

    for (int n=0;n<16;n++){
        const int time = bar*16 + n;
        float t0 = 0.f, t1 = 0.f;
        if (time > 0){
            const float* xr = x + ((size_t)bidx*TT + time-1)*PP;
            t0 = xr[lane];
            if (lane < 29) t1 = xr[32+lane];
        }
        float a0=sb[c0_], a1=sb[c1_], a2=sb[c2_], a3=sb[c3_];
        #pragma unroll
        for (int k=0;k<32;k++){
            float av = __shfl_sync(FULL, emb, k);
            a0 = fmaf(av, sWi[c0_*93+k], a0); a1 = fmaf(av, sWi[c1_*93+k], a1);
            a2 = fmaf(av, sWi[c2_*93+k], a2); a3 = fmaf(av, sWi[c3_*93+k], a3);
        }
        #pragma unroll
        for (int k=0;k<32;k++){
            float av = __shfl_sync(FULL, t0, k); const int kk=32+k;
            a0 = fmaf(av, sWi[c0_*93+kk], a0); a1 = fmaf(av, sWi[c1_*93+kk], a1);
            a2 = fmaf(av, sWi[c2_*93+kk], a2); a3 = fmaf(av, sWi[c3_*93+kk], a3);
        }
        #pragma unroll
        for (int k=0;k<29;k++){
            float av = __shfl_sync(FULL, t1, k); const int kk=64+k;
            a0 = fmaf(av, sWi[c0_*93+kk], a0); a1 = fmaf(av, sWi[c1_*93+kk], a1);
            a2 = fmaf(av, sWi[c2_*93+kk], a2); a3 = fmaf(av, sWi[c3_*93+kk], a3);
        }
        #pragma unroll
        for (int k=0;k<32;k++){
            float av = __shfl_sync(FULL, h, k);
            a0 = fmaf(av, sWh[c0_*33+k], a0); a1 = fmaf(av, sWh[c1_*33+k], a1);
            a2 = fmaf(av, sWh[c2_*33+k], a2); a3 = fmaf(av, sWh[c3_*33+k], a3);
        }
        float iv=sigmoidf_(a0), fv=sigmoidf_(a1), gv=tanhf(a2), ov=sigmoidf_(a3);
        c = fv*c + iv*gv;
        h = ov*tanhf(c);

        float l0 = sbl[lane], l1 = sbl[32+lane];
        #pragma unroll
        for (int k=0;k<32;k++){
            float hv = __shfl_sync(FULL, h, k);
            l0 = fmaf(hv, sWl[lane*33+k], l0);
            l1 = fmaf(hv, sWl[(32+lane)*33+k], l1);
        }
        float l1m = (lane < 29) ? l1 : -1e30f;
        float mx = fmaxf(l0, l1m);
        #pragma unroll
        for (int off=16; off; off>>=1) mx = fmaxf(mx, __shfl_xor_sync(FULL, mx, off));
        float e0 = __expf(l0 - mx);
        float e1 = (lane < 29) ? __expf(l1 - mx) : 0.f;
        float s = e0 + e1;
        #pragma unroll
        for (int off=16; off; off>>=1) s += __shfl_xor_sync(FULL, s, off);
        const float inv = 1.f/s;
        float* nr = notes + ((size_t)bidx*TT + time)*PP;
        nr[lane] = e0*inv;
        if (lane < 29) nr[32+lane] = e1*inv;
    }
}

// ---------------- launch ----------------
extern "C" void kernel_launch(void* const* d_in, const int* in_sizes, int n_in,
                              void* d_out, int out_size)
{
    const float* x        = (const float*)d_in[0];
    const float* eps      = (const float*)d_in[1];
    const float* dec_h0   = (const float*)d_in[2];
    const float* dec_c0   = (const float*)d_in[3];
    const float* eWih_f   = (const float*)d_in[4];
    const float* eWhh_f   = (const float*)d_in[5];
    const float* eb_f     = (const float*)d_in[6];
    const float* eWih_b   = (const float*)d_in[7];
    const float* eWhh_b   = (const float*)d_in[8];
    const float* eb_b     = (const float*)d_in[9];
    const float* Wout     = (const float*)d_in[10];
    const float* bout     = (const float*)d_in[11];
    const float* Wz       = (const float*)d_in[12];
    const float* bz       = (const float*)d_in[13];
    const float* conWih   = (const float*)d_in[14];
    const float* conWhh   = (const float*)d_in[15];
    const float* conb     = (const float*)d_in[16];
    const float* dWih     = (const float*)d_in[17];
    const float* dWhh     = (const float*)d_in[18];
    const float* db       = (const float*)d_in[19];
    const float* Wlin     = (const float*)d_in[20];
    const float* blin     = (const float*)d_in[21];

    float* out   = (float*)d_out;
    float* notes = out;
    float* zout  = out + (size_t)NROWS*PP;
    float* muo   = zout + (size_t)NROWS*DECD;
    float* lvo   = muo  + (size_t)NROWS*LATD;

    cudaFuncSetAttribute(xproj_kernel, cudaFuncAttributeMaxDynamicSharedMemorySize, 66048);
    xproj_kernel<<<dim3(32, TT, 2), 256, 66048>>>(x, eWih_f, eb_f, eWih_b, eb_b);

    cudaFuncSetAttribute(enc_persist_kernel, cudaFuncAttributeMaxDynamicSharedMemorySize, ENC_SMEM);
    enc_persist_kernel<<<NBLK, 512, ENC_SMEM>>>(eWhh_f, eWhh_b);

    cudaFuncSetAttribute(encout_mma_kernel, cudaFuncAttributeMaxDynamicSharedMemorySize, EO2_SMEM);
    encout_mma_kernel<<<dim3(8, NROWS/128), 256, EO2_SMEM>>>(Wout, bout, muo, lvo);

    zproj_kernel<<<NROWS/128, 256>>>(muo, lvo, eps, Wz, bz, zout);

    conductor_kernel<<<BB/8, 256>>>(zout, conWih, conWhh, conb);

    cudaFuncSetAttribute(decoder_kernel, cudaFuncAttributeMaxDynamicSharedMemorySize, 73728);
    decoder_kernel<<<(BB*TBAR)/8, 256, 73728>>>(x, dec_h0, dec_c0,
                                                dWih, dWhh, db, Wlin, blin, notes);
}